// round 13
// baseline (speedup 1.0000x reference)
#include <cuda_runtime.h>
#include <cuda_fp16.h>
#include <cstdint>

// Problem constants (LaplacianReg: B=32, V=65536, K=8, C=3)
#define BB 32
#define VV 65536
#define KK 8
#define CC 3
#define ROW (VV * CC)          // 196608 floats per batch row
#define VB (BB * CC)           // 96 halves per vertex in transposed scratch
#define RB (VB * 2)            // 192 bytes per vertex row (= 12 x 16B chunks)
#define VPB 64                 // vertices per block in kernel 2
#define SROW 100               // smem staging row stride (floats)

// fp16 transposed scratch: d16[v][b*3+c] = out[b][v][c] - tgt[b][v][c].
__device__ __align__(16) __half d16[(size_t)VV * VB];

typedef unsigned long long u64;

// half2 (packed in u32) -> packed f32x2: 2x F2F, pack coalesced by regalloc.
__device__ __forceinline__ u64 h2_to_f32x2(uint32_t h2) {
    u64 r;
    asm("{\n\t"
        ".reg .b16 l, h;\n\t"
        ".reg .f32 fl, fh;\n\t"
        "mov.b32 {l, h}, %1;\n\t"
        "cvt.f32.f16 fl, l;\n\t"
        "cvt.f32.f16 fh, h;\n\t"
        "mov.b64 %0, {fl, fh};\n\t"
        "}" : "=l"(r) : "r"(h2));
    return r;
}

__device__ __forceinline__ u64 ffma2(u64 a, u64 b, u64 c) {
    u64 d;
    asm("fma.rn.f32x2 %0, %1, %2, %3;" : "=l"(d) : "l"(a), "l"(b), "l"(c));
    return d;
}

__device__ __forceinline__ u64 fmul2(u64 a, u64 b) {
    u64 d;
    asm("mul.rn.f32x2 %0, %1, %2;" : "=l"(d) : "l"(a), "l"(b));
    return d;
}

// ---------------------------------------------------------------------------
// Kernel 1: fused difference + transpose (B,V,C) -> fp16 (V, B*C)
// ---------------------------------------------------------------------------
__global__ __launch_bounds__(256) void diff_transpose_kernel(
    const float* __restrict__ outp, const float* __restrict__ tgtp) {
    __shared__ float s[32 * 97];

    const int v0   = blockIdx.x * 32;
    const int warp = threadIdx.x >> 5;
    const int lane = threadIdx.x & 31;

    #pragma unroll
    for (int i = 0; i < 4; i++) {
        const int b = warp + 8 * i;
        const float* po = outp + (size_t)b * ROW + (size_t)v0 * CC;
        const float* pt = tgtp + (size_t)b * ROW + (size_t)v0 * CC;
        #pragma unroll
        for (int r = 0; r < 3; r++) {
            const int u = lane + 32 * r;
            s[b * 97 + u] = po[u] - pt[u];
        }
    }
    __syncthreads();

    #pragma unroll
    for (int i = 0; i < 4; i++) {
        const int vl = warp + 8 * i;
        if (lane < 24) {
            __half h[4];
            #pragma unroll
            for (int j = 0; j < 4; j++) {
                const int u = 4 * lane + j;       // 0..95
                const int b = u / 3;
                const int c = u - 3 * b;
                h[j] = __float2half_rn(s[b * 97 + vl * 3 + c]);
            }
            *reinterpret_cast<uint2*>(d16 + (size_t)(v0 + vl) * VB + 4 * lane) =
                *reinterpret_cast<const uint2*>(h);
        }
    }
}

// ---------------------------------------------------------------------------
// Kernel 2: 9-term gather laplacian + square, ALL 32 lanes active.
// A warp owns 8 vertices = 96 (vertex, 16B-chunk) lane-tasks = 3 iterations
// of 32 fully-active lanes. Per-lane: one LDG.128 per term (self + 8
// neighbors), packed f32x2 FMA accumulation, staged to smem, then written
// fully coalesced.
// ---------------------------------------------------------------------------
__global__ __launch_bounds__(256) void lap_sq_kernel(
    const int*   __restrict__ idx,
    const float* __restrict__ wgt,
    float*       __restrict__ res) {
    __shared__ int4   so4[VPB * 2];    // 8 byte-offsets (j*192) per vertex
    __shared__ float2 swd[VPB * KK];   // duplicated weights {w,w}
    __shared__ float  sn[VPB * SROW];  // (lap d)^2, vertex-major

    const int tid = threadIdx.x;
    const int v0  = blockIdx.x * VPB;

    // Stage byte offsets + duplicated weights (coalesced, 512 each).
    #pragma unroll
    for (int t = 0; t < (VPB * KK) / 256; t++) {
        const int i = t * 256 + tid;
        reinterpret_cast<int*>(so4)[i] = idx[(size_t)v0 * KK + i] * RB;
        const float w = wgt[(size_t)v0 * KK + i];
        swd[i] = make_float2(w, w);
    }
    __syncthreads();

    const int warp = tid >> 5;
    const int lane = tid & 31;
    const char* const dbase = reinterpret_cast<const char*>(d16);

    #pragma unroll
    for (int it3 = 0; it3 < 3; it3++) {
        const int g  = it3 * 32 + lane;   // 0..95 lane-task
        const int sv = g / 12;            // vertex-within-warp 0..7
        const int c  = g - sv * 12;       // 16B chunk 0..11
        const int vl = warp * 8 + sv;     // vertex-within-block

        // Per-lane neighbor byte-offsets + weights (divergent smem, no conflict).
        const int4 o0 = so4[vl * 2];
        const int4 o1 = so4[vl * 2 + 1];
        const u64* wp = reinterpret_cast<const u64*>(&swd[vl * KK]);
        const char* gbase = dbase + c * 16;

        // Batch 1: self + neighbors 0..3 (5 LDG.128 in flight).
        const uint4 gs = *reinterpret_cast<const uint4*>(gbase + (v0 + vl) * RB);
        const uint4 g0 = *reinterpret_cast<const uint4*>(gbase + o0.x);
        const uint4 g1 = *reinterpret_cast<const uint4*>(gbase + o0.y);
        const uint4 g2 = *reinterpret_cast<const uint4*>(gbase + o0.z);
        const uint4 g3 = *reinterpret_cast<const uint4*>(gbase + o0.w);

        u64 a0 = h2_to_f32x2(gs.x);
        u64 a1 = h2_to_f32x2(gs.y);
        u64 a2 = h2_to_f32x2(gs.z);
        u64 a3 = h2_to_f32x2(gs.w);

        {
            const u64 w0 = wp[0];
            a0 = ffma2(h2_to_f32x2(g0.x), w0, a0);
            a1 = ffma2(h2_to_f32x2(g0.y), w0, a1);
            a2 = ffma2(h2_to_f32x2(g0.z), w0, a2);
            a3 = ffma2(h2_to_f32x2(g0.w), w0, a3);
            const u64 w1 = wp[1];
            a0 = ffma2(h2_to_f32x2(g1.x), w1, a0);
            a1 = ffma2(h2_to_f32x2(g1.y), w1, a1);
            a2 = ffma2(h2_to_f32x2(g1.z), w1, a2);
            a3 = ffma2(h2_to_f32x2(g1.w), w1, a3);
            const u64 w2 = wp[2];
            a0 = ffma2(h2_to_f32x2(g2.x), w2, a0);
            a1 = ffma2(h2_to_f32x2(g2.y), w2, a1);
            a2 = ffma2(h2_to_f32x2(g2.z), w2, a2);
            a3 = ffma2(h2_to_f32x2(g2.w), w2, a3);
            const u64 w3 = wp[3];
            a0 = ffma2(h2_to_f32x2(g3.x), w3, a0);
            a1 = ffma2(h2_to_f32x2(g3.y), w3, a1);
            a2 = ffma2(h2_to_f32x2(g3.z), w3, a2);
            a3 = ffma2(h2_to_f32x2(g3.w), w3, a3);
        }

        // Batch 2: neighbors 4..7.
        const uint4 g4 = *reinterpret_cast<const uint4*>(gbase + o1.x);
        const uint4 g5 = *reinterpret_cast<const uint4*>(gbase + o1.y);
        const uint4 g6 = *reinterpret_cast<const uint4*>(gbase + o1.z);
        const uint4 g7 = *reinterpret_cast<const uint4*>(gbase + o1.w);
        {
            const u64 w4 = wp[4];
            a0 = ffma2(h2_to_f32x2(g4.x), w4, a0);
            a1 = ffma2(h2_to_f32x2(g4.y), w4, a1);
            a2 = ffma2(h2_to_f32x2(g4.z), w4, a2);
            a3 = ffma2(h2_to_f32x2(g4.w), w4, a3);
            const u64 w5 = wp[5];
            a0 = ffma2(h2_to_f32x2(g5.x), w5, a0);
            a1 = ffma2(h2_to_f32x2(g5.y), w5, a1);
            a2 = ffma2(h2_to_f32x2(g5.z), w5, a2);
            a3 = ffma2(h2_to_f32x2(g5.w), w5, a3);
            const u64 w6 = wp[6];
            a0 = ffma2(h2_to_f32x2(g6.x), w6, a0);
            a1 = ffma2(h2_to_f32x2(g6.y), w6, a1);
            a2 = ffma2(h2_to_f32x2(g6.z), w6, a2);
            a3 = ffma2(h2_to_f32x2(g6.w), w6, a3);
            const u64 w7 = wp[7];
            a0 = ffma2(h2_to_f32x2(g7.x), w7, a0);
            a1 = ffma2(h2_to_f32x2(g7.y), w7, a1);
            a2 = ffma2(h2_to_f32x2(g7.z), w7, a2);
            a3 = ffma2(h2_to_f32x2(g7.w), w7, a3);
        }

        // Square (packed) and stage: lane covers floats [c*8, c*8+8) of vl.
        a0 = fmul2(a0, a0);
        a1 = fmul2(a1, a1);
        a2 = fmul2(a2, a2);
        a3 = fmul2(a3, a3);
        u64* dst = reinterpret_cast<u64*>(&sn[vl * SROW + c * 8]);
        dst[0] = a0; dst[1] = a1; dst[2] = a2; dst[3] = a3;
    }
    __syncthreads();

    // Output phase: pure smem -> gmem, fully coalesced over res[b, v0:v0+64, :].
    const size_t base_o = (size_t)v0 * CC;
    #pragma unroll
    for (int it = 0; it < (BB * VPB * CC) / 256; it++) {   // 24 iterations
        const int i  = it * 256 + tid;
        const int b  = i / (VPB * CC);
        const int uu = i - b * (VPB * CC);                  // 0..191
        const int vl = uu / 3;
        const int cc = uu - 3 * vl;
        res[(size_t)b * ROW + base_o + uu] = sn[vl * SROW + b * CC + cc];
    }
}

extern "C" void kernel_launch(void* const* d_in, const int* in_sizes, int n_in,
                              void* d_out, int out_size) {
    const float* outp = (const float*)d_in[0];
    const float* tgtp = (const float*)d_in[1];
    const int*   idx  = (const int*)  d_in[2];
    const float* wgt  = (const float*)d_in[3];
    float*       res  = (float*)d_out;

    (void)in_sizes; (void)n_in; (void)out_size;

    diff_transpose_kernel<<<VV / 32, 256>>>(outp, tgtp);
    lap_sq_kernel<<<VV / VPB, 256>>>(idx, wgt, res);
}

// round 15
// speedup vs baseline: 1.4178x; 1.4178x over previous
#include <cuda_runtime.h>
#include <cuda_fp16.h>
#include <cstdint>

// Problem constants (LaplacianReg: B=32, V=65536, K=8, C=3)
#define BB 32
#define VV 65536
#define KK 8
#define CC 3
#define ROW (VV * CC)          // 196608 floats per batch row
#define VB (BB * CC)           // 96 halves per vertex in transposed scratch
#define RB (VB * 2)            // 192 bytes per vertex row (= 12 x 16B chunks)
#define VPB 32                 // vertices per block in kernel 2 (halved: occupancy)
#define SROW 100               // smem staging row stride (floats)

// fp16 transposed scratch: d16[v][b*3+c] = out[b][v][c] - tgt[b][v][c].
__device__ __align__(16) __half d16[(size_t)VV * VB];

typedef unsigned long long u64;

// half2 (packed in u32) -> packed f32x2: 2x F2F, pack coalesced by regalloc.
__device__ __forceinline__ u64 h2_to_f32x2(uint32_t h2) {
    u64 r;
    asm("{\n\t"
        ".reg .b16 l, h;\n\t"
        ".reg .f32 fl, fh;\n\t"
        "mov.b32 {l, h}, %1;\n\t"
        "cvt.f32.f16 fl, l;\n\t"
        "cvt.f32.f16 fh, h;\n\t"
        "mov.b64 %0, {fl, fh};\n\t"
        "}" : "=l"(r) : "r"(h2));
    return r;
}

__device__ __forceinline__ u64 ffma2(u64 a, u64 b, u64 c) {
    u64 d;
    asm("fma.rn.f32x2 %0, %1, %2, %3;" : "=l"(d) : "l"(a), "l"(b), "l"(c));
    return d;
}

__device__ __forceinline__ u64 fmul2(u64 a, u64 b) {
    u64 d;
    asm("mul.rn.f32x2 %0, %1, %2;" : "=l"(d) : "l"(a), "l"(b));
    return d;
}

// ---------------------------------------------------------------------------
// Kernel 1: fused difference + transpose (B,V,C) -> fp16 (V, B*C)
// ---------------------------------------------------------------------------
__global__ __launch_bounds__(256) void diff_transpose_kernel(
    const float* __restrict__ outp, const float* __restrict__ tgtp) {
    __shared__ float s[32 * 97];

    const int v0   = blockIdx.x * 32;
    const int warp = threadIdx.x >> 5;
    const int lane = threadIdx.x & 31;

    #pragma unroll
    for (int i = 0; i < 4; i++) {
        const int b = warp + 8 * i;
        const float* po = outp + (size_t)b * ROW + (size_t)v0 * CC;
        const float* pt = tgtp + (size_t)b * ROW + (size_t)v0 * CC;
        #pragma unroll
        for (int r = 0; r < 3; r++) {
            const int u = lane + 32 * r;
            s[b * 97 + u] = po[u] - pt[u];
        }
    }
    __syncthreads();

    #pragma unroll
    for (int i = 0; i < 4; i++) {
        const int vl = warp + 8 * i;
        if (lane < 24) {
            __half h[4];
            #pragma unroll
            for (int j = 0; j < 4; j++) {
                const int u = 4 * lane + j;       // 0..95
                const int b = u / 3;
                const int c = u - 3 * b;
                h[j] = __float2half_rn(s[b * 97 + vl * 3 + c]);
            }
            *reinterpret_cast<uint2*>(d16 + (size_t)(v0 + vl) * VB + 4 * lane) =
                *reinterpret_cast<const uint2*>(h);
        }
    }
}

// ---------------------------------------------------------------------------
// Kernel 2: 9-term gather laplacian + square (R12 structure, VPB=32).
// Paired-vertex LDG.128: lanes 0-11 hold vertex A's 12 16B-chunks, lanes
// 12-23 vertex B's, so ONE LDG.128 gathers neighbor k of both vertices.
// Packed fma.rn.f32x2 accumulation; weights pre-duplicated {w,w} in smem.
// Smem tile halved (18KB/block) so residency is warp-limited (~100% occ).
// ---------------------------------------------------------------------------
__global__ __launch_bounds__(256) void lap_sq_kernel(
    const int*   __restrict__ idx,
    const float* __restrict__ wgt,
    float*       __restrict__ res) {
    __shared__ int4   so4[VPB * 2];    // 8 byte-offsets (j*192) per vertex
    __shared__ float2 swd[VPB * KK];   // duplicated weights {w,w}
    __shared__ float  sn[VPB * SROW];  // (lap d)^2, vertex-major

    const int tid = threadIdx.x;
    const int v0  = blockIdx.x * VPB;

    // Stage byte offsets + duplicated weights (coalesced, 256 each).
    {
        const int i = tid;
        reinterpret_cast<int*>(so4)[i] = idx[(size_t)v0 * KK + i] * RB;
        const float w = wgt[(size_t)v0 * KK + i];
        swd[i] = make_float2(w, w);
    }
    __syncthreads();

    const int warp    = tid >> 5;
    const int lane    = tid & 31;
    const int h       = (lane >= 12) ? 1 : 0;   // vertex-within-pair
    const int c       = lane - h * 12;          // chunk 0..11
    const bool active = lane < 24;
    const char* gbase = reinterpret_cast<const char*>(d16) + c * 16;

    #pragma unroll
    for (int vp = 0; vp < 2; vp++) {
        const int vl = warp * 4 + 2 * vp + h;   // this lane's vertex

        // Pair-level smem reads (2 distinct addrs per warp, broadcast).
        const int4 o0 = so4[vl * 2];
        const int4 o1 = so4[vl * 2 + 1];
        const u64* wp = reinterpret_cast<const u64*>(&swd[vl * KK]);

        if (active) {
            // Batch 1: self + neighbors 0..3 (5 LDG.128 in flight).
            const uint4 gs = *reinterpret_cast<const uint4*>(gbase + (v0 + vl) * RB);
            const uint4 g0 = *reinterpret_cast<const uint4*>(gbase + o0.x);
            const uint4 g1 = *reinterpret_cast<const uint4*>(gbase + o0.y);
            const uint4 g2 = *reinterpret_cast<const uint4*>(gbase + o0.z);
            const uint4 g3 = *reinterpret_cast<const uint4*>(gbase + o0.w);

            u64 a0 = h2_to_f32x2(gs.x);
            u64 a1 = h2_to_f32x2(gs.y);
            u64 a2 = h2_to_f32x2(gs.z);
            u64 a3 = h2_to_f32x2(gs.w);

            {
                const u64 w0 = wp[0];
                a0 = ffma2(h2_to_f32x2(g0.x), w0, a0);
                a1 = ffma2(h2_to_f32x2(g0.y), w0, a1);
                a2 = ffma2(h2_to_f32x2(g0.z), w0, a2);
                a3 = ffma2(h2_to_f32x2(g0.w), w0, a3);
                const u64 w1 = wp[1];
                a0 = ffma2(h2_to_f32x2(g1.x), w1, a0);
                a1 = ffma2(h2_to_f32x2(g1.y), w1, a1);
                a2 = ffma2(h2_to_f32x2(g1.z), w1, a2);
                a3 = ffma2(h2_to_f32x2(g1.w), w1, a3);
                const u64 w2 = wp[2];
                a0 = ffma2(h2_to_f32x2(g2.x), w2, a0);
                a1 = ffma2(h2_to_f32x2(g2.y), w2, a1);
                a2 = ffma2(h2_to_f32x2(g2.z), w2, a2);
                a3 = ffma2(h2_to_f32x2(g2.w), w2, a3);
                const u64 w3 = wp[3];
                a0 = ffma2(h2_to_f32x2(g3.x), w3, a0);
                a1 = ffma2(h2_to_f32x2(g3.y), w3, a1);
                a2 = ffma2(h2_to_f32x2(g3.z), w3, a2);
                a3 = ffma2(h2_to_f32x2(g3.w), w3, a3);
            }

            // Batch 2: neighbors 4..7.
            const uint4 g4 = *reinterpret_cast<const uint4*>(gbase + o1.x);
            const uint4 g5 = *reinterpret_cast<const uint4*>(gbase + o1.y);
            const uint4 g6 = *reinterpret_cast<const uint4*>(gbase + o1.z);
            const uint4 g7 = *reinterpret_cast<const uint4*>(gbase + o1.w);
            {
                const u64 w4 = wp[4];
                a0 = ffma2(h2_to_f32x2(g4.x), w4, a0);
                a1 = ffma2(h2_to_f32x2(g4.y), w4, a1);
                a2 = ffma2(h2_to_f32x2(g4.z), w4, a2);
                a3 = ffma2(h2_to_f32x2(g4.w), w4, a3);
                const u64 w5 = wp[5];
                a0 = ffma2(h2_to_f32x2(g5.x), w5, a0);
                a1 = ffma2(h2_to_f32x2(g5.y), w5, a1);
                a2 = ffma2(h2_to_f32x2(g5.z), w5, a2);
                a3 = ffma2(h2_to_f32x2(g5.w), w5, a3);
                const u64 w6 = wp[6];
                a0 = ffma2(h2_to_f32x2(g6.x), w6, a0);
                a1 = ffma2(h2_to_f32x2(g6.y), w6, a1);
                a2 = ffma2(h2_to_f32x2(g6.z), w6, a2);
                a3 = ffma2(h2_to_f32x2(g6.w), w6, a3);
                const u64 w7 = wp[7];
                a0 = ffma2(h2_to_f32x2(g7.x), w7, a0);
                a1 = ffma2(h2_to_f32x2(g7.y), w7, a1);
                a2 = ffma2(h2_to_f32x2(g7.z), w7, a2);
                a3 = ffma2(h2_to_f32x2(g7.w), w7, a3);
            }

            // Square (packed) and stage: lane covers floats [c*8, c*8+8).
            a0 = fmul2(a0, a0);
            a1 = fmul2(a1, a1);
            a2 = fmul2(a2, a2);
            a3 = fmul2(a3, a3);
            u64* dst = reinterpret_cast<u64*>(&sn[vl * SROW + c * 8]);
            dst[0] = a0; dst[1] = a1; dst[2] = a2; dst[3] = a3;
        }
    }
    __syncthreads();

    // Output phase: pure smem -> gmem, fully coalesced over res[b, v0:v0+32, :].
    const size_t base_o = (size_t)v0 * CC;
    #pragma unroll
    for (int it = 0; it < (BB * VPB * CC) / 256; it++) {   // 12 iterations
        const int i  = it * 256 + tid;
        const int b  = i / (VPB * CC);
        const int uu = i - b * (VPB * CC);                  // 0..95
        const int vl = uu / 3;
        const int cc = uu - 3 * vl;
        res[(size_t)b * ROW + base_o + uu] = sn[vl * SROW + b * CC + cc];
    }
}

extern "C" void kernel_launch(void* const* d_in, const int* in_sizes, int n_in,
                              void* d_out, int out_size) {
    const float* outp = (const float*)d_in[0];
    const float* tgtp = (const float*)d_in[1];
    const int*   idx  = (const int*)  d_in[2];
    const float* wgt  = (const float*)d_in[3];
    float*       res  = (float*)d_out;

    (void)in_sizes; (void)n_in; (void)out_size;

    diff_transpose_kernel<<<VV / 32, 256>>>(outp, tgtp);
    lap_sq_kernel<<<VV / VPB, 256>>>(idx, wgt, res);
}

// round 16
// speedup vs baseline: 1.5366x; 1.0837x over previous
#include <cuda_runtime.h>
#include <cuda_fp16.h>
#include <cstdint>

// Problem constants (LaplacianReg: B=32, V=65536, K=8, C=3)
#define BB 32
#define VV 65536
#define KK 8
#define CC 3
#define ROW (VV * CC)          // 196608 floats per batch row
#define VB (BB * CC)           // 96 halves per vertex in transposed scratch
#define RB (VB * 2)            // 192 bytes per vertex row (= 12 x 16B chunks)
#define VPB 32                 // vertices per block in kernel 2
#define SROW 100               // smem staging row stride (floats)

// fp16 transposed scratch: d16[v][b*3+c] = out[b][v][c] - tgt[b][v][c].
__device__ __align__(16) __half d16[(size_t)VV * VB];

typedef unsigned long long u64;

// half2 (packed in u32) -> packed f32x2: 2x F2F, pack coalesced by regalloc.
__device__ __forceinline__ u64 h2_to_f32x2(uint32_t h2) {
    u64 r;
    asm("{\n\t"
        ".reg .b16 l, h;\n\t"
        ".reg .f32 fl, fh;\n\t"
        "mov.b32 {l, h}, %1;\n\t"
        "cvt.f32.f16 fl, l;\n\t"
        "cvt.f32.f16 fh, h;\n\t"
        "mov.b64 %0, {fl, fh};\n\t"
        "}" : "=l"(r) : "r"(h2));
    return r;
}

__device__ __forceinline__ u64 h2f(__half2 x) {
    uint32_t b;
    __builtin_memcpy(&b, &x, 4);
    return h2_to_f32x2(b);
}

__device__ __forceinline__ u64 fadd2(u64 a, u64 b) {
    u64 d;
    asm("add.rn.f32x2 %0, %1, %2;" : "=l"(d) : "l"(a), "l"(b));
    return d;
}

__device__ __forceinline__ u64 fmul2(u64 a, u64 b) {
    u64 d;
    asm("mul.rn.f32x2 %0, %1, %2;" : "=l"(d) : "l"(a), "l"(b));
    return d;
}

union U4H {
    uint4 u;
    __half2 h[4];
};

// ---------------------------------------------------------------------------
// Kernel 1: fused difference + transpose (B,V,C) -> fp16 (V, B*C)
// ---------------------------------------------------------------------------
__global__ __launch_bounds__(256) void diff_transpose_kernel(
    const float* __restrict__ outp, const float* __restrict__ tgtp) {
    __shared__ float s[32 * 97];

    const int v0   = blockIdx.x * 32;
    const int warp = threadIdx.x >> 5;
    const int lane = threadIdx.x & 31;

    #pragma unroll
    for (int i = 0; i < 4; i++) {
        const int b = warp + 8 * i;
        const float* po = outp + (size_t)b * ROW + (size_t)v0 * CC;
        const float* pt = tgtp + (size_t)b * ROW + (size_t)v0 * CC;
        #pragma unroll
        for (int r = 0; r < 3; r++) {
            const int u = lane + 32 * r;
            s[b * 97 + u] = po[u] - pt[u];
        }
    }
    __syncthreads();

    #pragma unroll
    for (int i = 0; i < 4; i++) {
        const int vl = warp + 8 * i;
        if (lane < 24) {
            __half h[4];
            #pragma unroll
            for (int j = 0; j < 4; j++) {
                const int u = 4 * lane + j;       // 0..95
                const int b = u / 3;
                const int c = u - 3 * b;
                h[j] = __float2half_rn(s[b * 97 + vl * 3 + c]);
            }
            *reinterpret_cast<uint2*>(d16 + (size_t)(v0 + vl) * VB + 4 * lane) =
                *reinterpret_cast<const uint2*>(h);
        }
    }
}

// ---------------------------------------------------------------------------
// Kernel 2: 9-term gather laplacian + square (R15 structure).
// NEW: neighbor accumulation in fp16 (HMUL2 + 7xHFMA2 per half2-word); only
// the neighbor SUM and the self term are converted to f32x2, added, squared.
// Converts/FFMA2 per word drop from 18cvt+8FFMA2 to 8HFMA2+4cvt+1ADD2+1MUL2.
// Precision: neighbor partial sums have ~0.35 sigma magnitude, so fp16
// rounding adds only ~1.3e-4 RMS on top of the 3.75e-4 storage error.
// ---------------------------------------------------------------------------
__global__ __launch_bounds__(256) void lap_sq_kernel(
    const int*   __restrict__ idx,
    const float* __restrict__ wgt,
    float*       __restrict__ res) {
    __shared__ int4    so4[VPB * 2];    // 8 byte-offsets (j*192) per vertex
    __shared__ __half2 swh[VPB * KK];   // duplicated fp16 weights {w,w}
    __shared__ float   sn[VPB * SROW];  // (lap d)^2, vertex-major

    const int tid = threadIdx.x;
    const int v0  = blockIdx.x * VPB;

    // Stage byte offsets + duplicated fp16 weights (coalesced, 256 each).
    {
        const int i = tid;
        reinterpret_cast<int*>(so4)[i] = idx[(size_t)v0 * KK + i] * RB;
        swh[i] = __float2half2_rn(wgt[(size_t)v0 * KK + i]);
    }
    __syncthreads();

    const int warp    = tid >> 5;
    const int lane    = tid & 31;
    const int h       = (lane >= 12) ? 1 : 0;   // vertex-within-pair
    const int c       = lane - h * 12;          // chunk 0..11
    const bool active = lane < 24;
    const char* gbase = reinterpret_cast<const char*>(d16) + c * 16;

    #pragma unroll
    for (int vp = 0; vp < 2; vp++) {
        const int vl = warp * 4 + 2 * vp + h;   // this lane's vertex

        // Pair-level smem reads (2 distinct addrs per warp, broadcast).
        const int4 o0 = so4[vl * 2];
        const int4 o1 = so4[vl * 2 + 1];
        U4H W0, W1;                              // 8 fp16x2 weights: 2 LDS.128
        W0.u = *reinterpret_cast<const uint4*>(&swh[vl * KK]);
        W1.u = *reinterpret_cast<const uint4*>(&swh[vl * KK + 4]);

        if (active) {
            // Issue all 9 LDG.128 (self + 8 neighbors) before consuming.
            U4H gs, g0, g1, g2, g3, g4, g5, g6, g7;
            gs.u = *reinterpret_cast<const uint4*>(gbase + (v0 + vl) * RB);
            g0.u = *reinterpret_cast<const uint4*>(gbase + o0.x);
            g1.u = *reinterpret_cast<const uint4*>(gbase + o0.y);
            g2.u = *reinterpret_cast<const uint4*>(gbase + o0.z);
            g3.u = *reinterpret_cast<const uint4*>(gbase + o0.w);
            g4.u = *reinterpret_cast<const uint4*>(gbase + o1.x);
            g5.u = *reinterpret_cast<const uint4*>(gbase + o1.y);
            g6.u = *reinterpret_cast<const uint4*>(gbase + o1.z);
            g7.u = *reinterpret_cast<const uint4*>(gbase + o1.w);

            u64 out[4];
            #pragma unroll
            for (int j = 0; j < 4; j++) {
                // Neighbor sum in fp16 (intermediates ~0.35 sigma: safe).
                __half2 n = __hmul2(W0.h[0], g0.h[j]);
                n = __hfma2(W0.h[1], g1.h[j], n);
                n = __hfma2(W0.h[2], g2.h[j], n);
                n = __hfma2(W0.h[3], g3.h[j], n);
                n = __hfma2(W1.h[0], g4.h[j], n);
                n = __hfma2(W1.h[1], g5.h[j], n);
                n = __hfma2(W1.h[2], g6.h[j], n);
                n = __hfma2(W1.h[3], g7.h[j], n);
                // Finish in packed fp32: self + nsum, then square.
                u64 a = fadd2(h2f(gs.h[j]), h2f(n));
                out[j] = fmul2(a, a);
            }

            u64* dst = reinterpret_cast<u64*>(&sn[vl * SROW + c * 8]);
            dst[0] = out[0]; dst[1] = out[1]; dst[2] = out[2]; dst[3] = out[3];
        }
    }
    __syncthreads();

    // Output phase: pure smem -> gmem, fully coalesced over res[b, v0:v0+32, :].
    const size_t base_o = (size_t)v0 * CC;
    #pragma unroll
    for (int it = 0; it < (BB * VPB * CC) / 256; it++) {   // 12 iterations
        const int i  = it * 256 + tid;
        const int b  = i / (VPB * CC);
        const int uu = i - b * (VPB * CC);                  // 0..95
        const int vl = uu / 3;
        const int cc = uu - 3 * vl;
        res[(size_t)b * ROW + base_o + uu] = sn[vl * SROW + b * CC + cc];
    }
}

extern "C" void kernel_launch(void* const* d_in, const int* in_sizes, int n_in,
                              void* d_out, int out_size) {
    const float* outp = (const float*)d_in[0];
    const float* tgtp = (const float*)d_in[1];
    const int*   idx  = (const int*)  d_in[2];
    const float* wgt  = (const float*)d_in[3];
    float*       res  = (float*)d_out;

    (void)in_sizes; (void)n_in; (void)out_size;

    diff_transpose_kernel<<<VV / 32, 256>>>(outp, tgtp);
    lap_sq_kernel<<<VV / VPB, 256>>>(idx, wgt, res);
}